// round 5
// baseline (speedup 1.0000x reference)
#include <cuda_runtime.h>
#include <math.h>
#include <stdint.h>

#define NB 256
#define NT 100
#define NI 1024
#define NH 2048
#define NO 1024

// ---------------------------------------------------------------------------
// Static device state.
// ---------------------------------------------------------------------------
__device__ float g_p1[NB * NI];
__device__ float g_p2[NB * NH];
__device__ int8_t g_s1[NB * NI];
__device__ int8_t g_s2[NB * NH];
__device__ float g_acc[NB * NO];
__device__ float g_df1[NI];
__device__ float g_df2[NH];
__device__ float g_tw[NT];
// 4 balanced base-128 int8 digits per weight: w ~= 2^-28 * sum d_i * 128^i,
// |d_i| <= 64. Products with binary spikes are exact integers in s32 IMMA.
__device__ int8_t g_W1L[4][NH * NI];
__device__ int8_t g_W2L[4][NO * NH];

// ---------------------------------------------------------------------------
// PTX helpers (arch-agnostic sm_80+: cp.async / ldmatrix / imma)
// ---------------------------------------------------------------------------
__device__ __forceinline__ uint32_t smem_u32(const void* p) {
    uint32_t a;
    asm("{ .reg .u64 t; cvta.to.shared.u64 t, %1; cvt.u32.u64 %0, t; }" : "=r"(a) : "l"(p));
    return a;
}
__device__ __forceinline__ void cp16(uint32_t s, const void* g) {
    asm volatile("cp.async.cg.shared.global [%0], [%1], 16;" :: "r"(s), "l"(g));
}
#define CP_COMMIT() asm volatile("cp.async.commit_group;" ::: "memory")
#define CP_WAIT(n)  asm volatile("cp.async.wait_group %0;" :: "n"(n) : "memory")

__device__ __forceinline__ void ldsm4(uint32_t* r, uint32_t addr) {
    asm volatile("ldmatrix.sync.aligned.m8n8.x4.shared.b16 {%0,%1,%2,%3}, [%4];"
                 : "=r"(r[0]), "=r"(r[1]), "=r"(r[2]), "=r"(r[3]) : "r"(addr));
}
__device__ __forceinline__ void ldsm2(uint32_t* r, uint32_t addr) {
    asm volatile("ldmatrix.sync.aligned.m8n8.x2.shared.b16 {%0,%1}, [%2];"
                 : "=r"(r[0]), "=r"(r[1]) : "r"(addr));
}
__device__ __forceinline__ void imma16832(int32_t* c, const uint32_t* a, const uint32_t* b) {
    asm volatile("mma.sync.aligned.m16n8k32.row.col.s32.s8.s8.s32 "
                 "{%0,%1,%2,%3}, {%4,%5,%6,%7}, {%8,%9}, {%0,%1,%2,%3};"
                 : "+r"(c[0]), "+r"(c[1]), "+r"(c[2]), "+r"(c[3])
                 : "r"(a[0]), "r"(a[1]), "r"(a[2]), "r"(a[3]), "r"(b[0]), "r"(b[1]));
}

// ---------------------------------------------------------------------------
// Setup kernels
// ---------------------------------------------------------------------------
__global__ void init_kernel(const float* __restrict__ cd1, const float* __restrict__ v1,
                            const float* __restrict__ cd2, const float* __restrict__ v2) {
    int idx = blockIdx.x * blockDim.x + threadIdx.x;
    if (idx < NB * NH) g_p2[idx] = 0.0f;
    if (idx < NB * NI) g_p1[idx] = 0.0f;
    if (idx < NB * NO) g_acc[idx] = 0.0f;
    if (idx < NI) {
        float vc = fminf(fmaxf(v1[0], 0.0f), 0.999f);
        float gamma = 1.0f / sqrtf(1.0f - vc * vc);
        g_df1[idx] = expf(-(gamma * fabsf(cd1[idx]) * vc));
    }
    if (idx < NH) {
        float vc = fminf(fmaxf(v2[0], 0.0f), 0.999f);
        float gamma = 1.0f / sqrtf(1.0f - vc * vc);
        g_df2[idx] = expf(-(gamma * fabsf(cd2[idx]) * vc));
    }
}

__device__ __forceinline__ void make_digits(float w, int8_t* out, size_t stride, size_t idx) {
    long long q = llrintf(w * 268435456.0f);  // w * 2^28
#pragma unroll
    for (int i = 0; i < 4; i++) {
        int d = (int)(((q + 64) & 127) - 64);
        out[i * stride + idx] = (int8_t)d;
        q = (q - d) >> 7;
    }
}

__global__ void limbs_kernel(const float* __restrict__ W1, const float* __restrict__ W2) {
    size_t idx = (size_t)blockIdx.x * blockDim.x + threadIdx.x;
    if (idx < (size_t)NH * NI) make_digits(W1[idx], &g_W1L[0][0], (size_t)NH * NI, idx);
    if (idx < (size_t)NO * NH) make_digits(W2[idx], &g_W2L[0][0], (size_t)NO * NH, idx);
}

__global__ void tw_kernel(const float* __restrict__ v1) {
    __shared__ float sh[128];
    int t = threadIdx.x;
    float vc = fminf(fmaxf(v1[0], 0.0f), 0.999f);
    float gamma = 1.0f / sqrtf(1.0f - vc * vc);
    float e = (t < NT) ? expf(-(gamma - 1.0f) * (float)t) : 0.0f;
    sh[t] = e;
    __syncthreads();
    for (int s = 64; s > 0; s >>= 1) {
        if (t < s) sh[t] += sh[t + s];
        __syncthreads();
    }
    if (t < NT) g_tw[t] = e / sh[0];
}

__global__ void lif1_first(const float* __restrict__ x) {
    int idx = blockIdx.x * blockDim.x + threadIdx.x;  // over NB*NI
    int b = idx / NI, i = idx % NI;
    float p = x[b * (NT * NI) + i] * g_df1[i];
    bool s = p > 1.0f;
    g_s1[idx] = s ? 1 : 0;
    g_p1[idx] = s ? 0.0f : p;
}

// ---------------------------------------------------------------------------
// IMMA GEMM + fused LIF epilogue. 256 threads, 8 warps.
// WHICH==1: h = s1 @ W1^T (+b1) -> LIF2 -> s2,p2.  M=256,N=2048,K=1024.
//           BM=128, BN=32, grid (64,2)=128. Warps 4x2, warp tile 32x16.
// WHICH==2: o = s2 @ W2^T; acc += tw*o; LIF1(t+1).  M=256,N=1024,K=2048.
//           BM=64, BN=32, grid (32,4)=128. Warps 2x4, warp tile 32x8.
// K in 128-byte chunks (conflict-free XOR swizzle), 3-stage cp.async pipeline.
// 4 separate s32 accumulators per output (one per digit), exact combine in
// the epilogue: h = float(double(((d3*128+d2)*128+d1)*128+d0_acc) * 2^-28).
// ---------------------------------------------------------------------------
template <int WHICH>
__global__ void __launch_bounds__(256, 1) snn_imma(const float* __restrict__ b1,
                                                   const float* __restrict__ x, int t) {
    constexpr int K    = (WHICH == 1) ? NI : NH;
    constexpr int NOUT = (WHICH == 1) ? NH : NO;
    constexpr int BM   = (WHICH == 1) ? 128 : 64;
    constexpr int BN   = 32;
    constexpr int NT4  = (WHICH == 1) ? 2 : 1;   // n8 tiles per warp
    constexpr int NCH  = K / 128;
    constexpr int ABYTES = BM * 128;
    constexpr int BBYTES = 4 * BN * 128;
    constexpr int STAGE  = ABYTES + BBYTES;
    constexpr size_t LSTR = (size_t)NH * NI;

    const int8_t* A  = (WHICH == 1) ? g_s1 : g_s2;
    const int8_t* BL = (WHICH == 1) ? &g_W1L[0][0] : &g_W2L[0][0];

    extern __shared__ char smem[];
    uint32_t sb = smem_u32(smem);

    int tid = threadIdx.x, lane = tid & 31, w = tid >> 5;
    int m0 = blockIdx.y * BM, n0 = blockIdx.x * BN;
    int wm = (WHICH == 1) ? (w & 3) * 32 : (w & 1) * 32;
    int wn = (WHICH == 1) ? (w >> 2) * 16 : (w >> 1) * 8;

    // ---- chunk loader: A tile BMx128B + B tiles 4x(BNx128B), XOR swizzle ----
    auto load_chunk = [&](int kc, int stg) {
        uint32_t abase = sb + stg * STAGE;
        uint32_t bbase = abase + ABYTES;
#pragma unroll
        for (int p = 0; p < BM * 8 / 256; p++) {
            int idx = p * 256 + tid;
            int row = idx >> 3, q = idx & 7;
            cp16(abase + row * 128 + ((q ^ (row & 7)) << 4),
                 A + (size_t)(m0 + row) * K + kc * 128 + q * 16);
        }
#pragma unroll
        for (int p = 0; p < 4; p++) {
            int idx = p * 256 + tid;
            int l = idx >> 8, rem = idx & 255, row = rem >> 3, q = rem & 7;
            cp16(bbase + l * (BN * 128) + row * 128 + ((q ^ (row & 7)) << 4),
                 BL + (size_t)l * LSTR + (size_t)(n0 + row) * K + kc * 128 + q * 16);
        }
        CP_COMMIT();
    };

    int32_t acc[4][2][NT4][4] = {};

    load_chunk(0, 0);
    load_chunk(1, 1);

    for (int c = 0; c < NCH; c++) {
        int stg = c % 3;
        if (c + 2 < NCH) { load_chunk(c + 2, (c + 2) % 3); CP_WAIT(2); }
        else if (c + 1 < NCH) { CP_WAIT(1); }
        else { CP_WAIT(0); }
        __syncthreads();

        uint32_t abase = sb + stg * STAGE;
        uint32_t bbase = abase + ABYTES;
        int j = lane >> 3, r = lane & 7;

#pragma unroll
        for (int ks = 0; ks < 4; ks++) {
            uint32_t a[2][4];
#pragma unroll
            for (int mt = 0; mt < 2; mt++) {
                int row = wm + mt * 16 + ((j & 1) << 3) + r;
                int slot = (ks * 2 + (j >> 1)) ^ (row & 7);
                ldsm4(a[mt], abase + row * 128 + slot * 16);
            }
#pragma unroll
            for (int l = 0; l < 4; l++) {
                if (WHICH == 1) {
                    uint32_t b[4];
                    int row = wn + ((j >> 1) << 3) + r;
                    int slot = (ks * 2 + (j & 1)) ^ (row & 7);
                    ldsm4(b, bbase + l * (BN * 128) + row * 128 + slot * 16);
#pragma unroll
                    for (int mt = 0; mt < 2; mt++) {
                        imma16832(acc[l][mt][0], a[mt], &b[0]);
                        imma16832(acc[l][mt][1], a[mt], &b[2]);
                    }
                } else {
                    uint32_t b[2];
                    int row = wn + r;
                    int jj = j & 1;
                    int slot = (ks * 2 + jj) ^ (row & 7);
                    ldsm2(b, bbase + l * (BN * 128) + row * 128 + slot * 16);
#pragma unroll
                    for (int mt = 0; mt < 2; mt++)
                        imma16832(acc[l][mt][0], a[mt], b);
                }
            }
        }
        __syncthreads();
    }

    // ---- exact combine + fused LIF epilogue ----
    const double SCALE = 3.7252902984619140625e-09;  // 2^-28
    int qr = lane >> 2, qc = (lane & 3) * 2;
#pragma unroll
    for (int mt = 0; mt < 2; mt++) {
#pragma unroll
        for (int h = 0; h < 2; h++) {
            int m = m0 + wm + mt * 16 + qr + h * 8;
#pragma unroll
            for (int nt = 0; nt < NT4; nt++) {
                int n = n0 + wn + nt * 8 + qc;
                long long T0 = acc[3][mt][nt][h * 2];
                T0 = (T0 << 7) + acc[2][mt][nt][h * 2];
                T0 = (T0 << 7) + acc[1][mt][nt][h * 2];
                T0 = (T0 << 7) + acc[0][mt][nt][h * 2];
                long long T1 = acc[3][mt][nt][h * 2 + 1];
                T1 = (T1 << 7) + acc[2][mt][nt][h * 2 + 1];
                T1 = (T1 << 7) + acc[1][mt][nt][h * 2 + 1];
                T1 = (T1 << 7) + acc[0][mt][nt][h * 2 + 1];
                float v0 = (float)((double)T0 * SCALE);
                float v1 = (float)((double)T1 * SCALE);
                size_t idx = (size_t)m * NOUT + n;
                if (WHICH == 1) {
                    float2 bv = *(const float2*)(b1 + n);
                    float2 fv = *(const float2*)(g_df2 + n);
                    float2 pv = *(float2*)(g_p2 + idx);
                    float p0 = pv.x * 0.9f + (v0 + bv.x) * fv.x;
                    float p1 = pv.y * 0.9f + (v1 + bv.y) * fv.y;
                    bool s0 = p0 > 0.8f, s1 = p1 > 0.8f;
                    *(float2*)(g_p2 + idx) = make_float2(s0 ? 0.f : p0, s1 ? 0.f : p1);
                    char2 sv; sv.x = s0 ? 1 : 0; sv.y = s1 ? 1 : 0;
                    *(char2*)(g_s2 + idx) = sv;
                } else {
                    float tw = g_tw[t];
                    float2 av = *(float2*)(g_acc + idx);
                    av.x += tw * v0;
                    av.y += tw * v1;
                    *(float2*)(g_acc + idx) = av;
                    if (t + 1 < NT) {
                        float2 xv = *(const float2*)(x + (size_t)m * (NT * NI) +
                                                     (size_t)(t + 1) * NI + n);
                        float2 fv = *(const float2*)(g_df1 + n);
                        float2 pv = *(float2*)(g_p1 + idx);
                        float p0 = pv.x * 0.9f + xv.x * fv.x;
                        float p1 = pv.y * 0.9f + xv.y * fv.y;
                        bool s0 = p0 > 1.0f, s1 = p1 > 1.0f;
                        *(float2*)(g_p1 + idx) = make_float2(s0 ? 0.f : p0, s1 ? 0.f : p1);
                        char2 sv; sv.x = s0 ? 1 : 0; sv.y = s1 ? 1 : 0;
                        *(char2*)(g_s1 + idx) = sv;
                    }
                }
            }
        }
    }
}

// Final: out = (acc + b2) * out_scale + out_bias  (sum_t tw == 1 absorbs b2).
__global__ void final_kernel(const float* __restrict__ b2, const float* __restrict__ osc,
                             const float* __restrict__ obi, float* __restrict__ out) {
    int idx = blockIdx.x * blockDim.x + threadIdx.x;
    int o = idx & (NO - 1);
    out[idx] = (g_acc[idx] + b2[o]) * osc[o] + obi[o];
}

// ---------------------------------------------------------------------------
extern "C" void kernel_launch(void* const* d_in, const int* in_sizes, int n_in,
                              void* d_out, int out_size) {
    const float* x   = (const float*)d_in[0];
    const float* cd1 = (const float*)d_in[1];
    const float* v1  = (const float*)d_in[2];
    const float* cd2 = (const float*)d_in[3];
    const float* v2  = (const float*)d_in[4];
    const float* W1  = (const float*)d_in[5];
    const float* b1  = (const float*)d_in[6];
    const float* W2  = (const float*)d_in[7];
    const float* b2  = (const float*)d_in[8];
    const float* osc = (const float*)d_in[9];
    const float* obi = (const float*)d_in[10];
    float* out = (float*)d_out;

    constexpr int SMEM1 = 3 * (128 * 128 + 4 * 32 * 128);  // 98304
    constexpr int SMEM2 = 3 * (64 * 128 + 4 * 32 * 128);   // 73728
    cudaFuncSetAttribute(snn_imma<1>, cudaFuncAttributeMaxDynamicSharedMemorySize, SMEM1);
    cudaFuncSetAttribute(snn_imma<2>, cudaFuncAttributeMaxDynamicSharedMemorySize, SMEM2);

    init_kernel<<<(NB * NH + 255) / 256, 256>>>(cd1, v1, cd2, v2);
    limbs_kernel<<<(NH * NI + 255) / 256, 256>>>(W1, W2);
    tw_kernel<<<1, 128>>>(v1);
    lif1_first<<<(NB * NI) / 256, 256>>>(x);

    for (int t = 0; t < NT; t++) {
        snn_imma<1><<<dim3(NH / 32, NB / 128), 256, SMEM1>>>(b1, x, t);
        snn_imma<2><<<dim3(NO / 32, NB / 64), 256, SMEM2>>>(b1, x, t);
    }

    final_kernel<<<(NB * NO) / 256, 256>>>(b2, osc, obi, out);
}

// round 6
// speedup vs baseline: 2.4056x; 2.4056x over previous
#include <cuda_runtime.h>
#include <cuda_fp16.h>
#include <math.h>
#include <stdint.h>

#define NB 256
#define NT 100
#define NI 1024
#define NH 2048
#define NO 1024

// ---------------------------------------------------------------------------
// Static device state.
// ---------------------------------------------------------------------------
__device__ float g_p1[NB * NI];
__device__ float g_p2[NB * NH];
__device__ __half g_s1[NB * NI];
__device__ __half g_s2[NB * NH];
__device__ float g_acc[NB * NO];
__device__ float g_df1[NI];
__device__ float g_df2[NH];
__device__ float g_tw[NT];
// 2 fp16 integer digits per weight: q = round(w*2^26) = d1*4096 + d0,
// digits in [-2048, 2048] (exact in fp16). Spike products are exact integers;
// fp32 HMMA accumulation is exact (sums <= 2^22).
__device__ __half g_W1L[2][NH * NI];
__device__ __half g_W2L[2][NO * NH];

// ---------------------------------------------------------------------------
// PTX helpers (arch-agnostic sm_80+: cp.async / ldmatrix / mma)
// ---------------------------------------------------------------------------
__device__ __forceinline__ uint32_t smem_u32(const void* p) {
    uint32_t a;
    asm("{ .reg .u64 t; cvta.to.shared.u64 t, %1; cvt.u32.u64 %0, t; }" : "=r"(a) : "l"(p));
    return a;
}
__device__ __forceinline__ void cp16(uint32_t s, const void* g) {
    asm volatile("cp.async.cg.shared.global [%0], [%1], 16;" :: "r"(s), "l"(g));
}
#define CP_COMMIT() asm volatile("cp.async.commit_group;" ::: "memory")
#define CP_WAIT(n)  asm volatile("cp.async.wait_group %0;" :: "n"(n) : "memory")

__device__ __forceinline__ void ldsm4(uint32_t* r, uint32_t addr) {
    asm volatile("ldmatrix.sync.aligned.m8n8.x4.shared.b16 {%0,%1,%2,%3}, [%4];"
                 : "=r"(r[0]), "=r"(r[1]), "=r"(r[2]), "=r"(r[3]) : "r"(addr));
}
__device__ __forceinline__ void ldsm2(uint32_t* r, uint32_t addr) {
    asm volatile("ldmatrix.sync.aligned.m8n8.x2.shared.b16 {%0,%1}, [%2];"
                 : "=r"(r[0]), "=r"(r[1]) : "r"(addr));
}
__device__ __forceinline__ void hmma16816(float* c, const uint32_t* a, const uint32_t* b) {
    asm volatile("mma.sync.aligned.m16n8k16.row.col.f32.f16.f16.f32 "
                 "{%0,%1,%2,%3}, {%4,%5,%6,%7}, {%8,%9}, {%0,%1,%2,%3};"
                 : "+f"(c[0]), "+f"(c[1]), "+f"(c[2]), "+f"(c[3])
                 : "r"(a[0]), "r"(a[1]), "r"(a[2]), "r"(a[3]), "r"(b[0]), "r"(b[1]));
}

// ---------------------------------------------------------------------------
// Setup kernels
// ---------------------------------------------------------------------------
__global__ void init_kernel(const float* __restrict__ cd1, const float* __restrict__ v1,
                            const float* __restrict__ cd2, const float* __restrict__ v2) {
    int idx = blockIdx.x * blockDim.x + threadIdx.x;
    if (idx < NB * NH) g_p2[idx] = 0.0f;
    if (idx < NB * NI) g_p1[idx] = 0.0f;
    if (idx < NB * NO) g_acc[idx] = 0.0f;
    if (idx < NI) {
        float vc = fminf(fmaxf(v1[0], 0.0f), 0.999f);
        float gamma = 1.0f / sqrtf(1.0f - vc * vc);
        g_df1[idx] = expf(-(gamma * fabsf(cd1[idx]) * vc));
    }
    if (idx < NH) {
        float vc = fminf(fmaxf(v2[0], 0.0f), 0.999f);
        float gamma = 1.0f / sqrtf(1.0f - vc * vc);
        g_df2[idx] = expf(-(gamma * fabsf(cd2[idx]) * vc));
    }
}

__device__ __forceinline__ void make_digits(float w, __half* out, size_t stride, size_t idx) {
    long long q = llrintf(w * 67108864.0f);  // w * 2^26
    if (q > 8388607LL) q = 8388607LL;
    if (q < -8388607LL) q = -8388607LL;
    int d0 = (int)(((q + 2048) & 4095) - 2048);
    int d1 = (int)((q - d0) >> 12);           // in [-2048, 2048], exact in fp16
    out[idx] = __int2half_rn(d0);
    out[stride + idx] = __int2half_rn(d1);
}

__global__ void limbs_kernel(const float* __restrict__ W1, const float* __restrict__ W2) {
    size_t idx = (size_t)blockIdx.x * blockDim.x + threadIdx.x;
    if (idx < (size_t)NH * NI) make_digits(W1[idx], &g_W1L[0][0], (size_t)NH * NI, idx);
    if (idx < (size_t)NO * NH) make_digits(W2[idx], &g_W2L[0][0], (size_t)NO * NH, idx);
}

__global__ void tw_kernel(const float* __restrict__ v1) {
    __shared__ float sh[128];
    int t = threadIdx.x;
    float vc = fminf(fmaxf(v1[0], 0.0f), 0.999f);
    float gamma = 1.0f / sqrtf(1.0f - vc * vc);
    float e = (t < NT) ? expf(-(gamma - 1.0f) * (float)t) : 0.0f;
    sh[t] = e;
    __syncthreads();
    for (int s = 64; s > 0; s >>= 1) {
        if (t < s) sh[t] += sh[t + s];
        __syncthreads();
    }
    if (t < NT) g_tw[t] = e / sh[0];
}

__global__ void lif1_first(const float* __restrict__ x) {
    int idx = blockIdx.x * blockDim.x + threadIdx.x;  // over NB*NI
    int b = idx / NI, i = idx % NI;
    float p = x[b * (NT * NI) + i] * g_df1[i];
    bool s = p > 1.0f;
    g_s1[idx] = __float2half(s ? 1.0f : 0.0f);
    g_p1[idx] = s ? 0.0f : p;
}

// ---------------------------------------------------------------------------
// HMMA GEMM + fused LIF epilogue. 256 threads, 8 warps.
// WHICH==1: h = s1 @ W1^T (+b1) -> LIF2 -> s2,p2.  M=256,N=2048,K=1024.
//           BM=128, BN=32, grid (64,2)=128. Warps 4x2, warp tile 32x16.
// WHICH==2: o = s2 @ W2^T; acc += tw*o; LIF1(t+1).  M=256,N=1024,K=2048.
//           BM=64, BN=32, grid (32,4)=128. Warps 2x4, warp tile 32x8.
// K in 64-element (128B) chunks, XOR-swizzled rows, 3-stage cp.async pipeline.
// Separate fp32 accumulators per digit (exact); combine in double at epilogue.
// ---------------------------------------------------------------------------
template <int WHICH>
__global__ void __launch_bounds__(256, 1) snn_hmma(const float* __restrict__ b1,
                                                   const float* __restrict__ x, int t) {
    constexpr int K    = (WHICH == 1) ? NI : NH;
    constexpr int NOUT = (WHICH == 1) ? NH : NO;
    constexpr int BM   = (WHICH == 1) ? 128 : 64;
    constexpr int BN   = 32;
    constexpr int NT4  = (WHICH == 1) ? 2 : 1;   // n8 tiles per warp
    constexpr int NCH  = K / 64;
    constexpr int ABYTES = BM * 128;
    constexpr int BBYTES = 2 * BN * 128;
    constexpr int STAGE  = ABYTES + BBYTES;
    constexpr size_t LSTR = (size_t)NH * NI;

    const __half* A  = (WHICH == 1) ? g_s1 : g_s2;
    const __half* BL = (WHICH == 1) ? &g_W1L[0][0] : &g_W2L[0][0];

    extern __shared__ char smem[];
    uint32_t sb = smem_u32(smem);

    int tid = threadIdx.x, lane = tid & 31, w = tid >> 5;
    int m0 = blockIdx.y * BM, n0 = blockIdx.x * BN;
    int wm = (WHICH == 1) ? (w & 3) * 32 : (w & 1) * 32;
    int wn = (WHICH == 1) ? (w >> 2) * 16 : (w >> 1) * 8;

    // ---- chunk loader: A tile BMx128B + B tiles 2x(BNx128B), XOR swizzle ----
    auto load_chunk = [&](int kc, int stg) {
        uint32_t abase = sb + stg * STAGE;
        uint32_t bbase = abase + ABYTES;
#pragma unroll
        for (int p = 0; p < BM * 8 / 256; p++) {
            int idx = p * 256 + tid;
            int row = idx >> 3, q = idx & 7;
            cp16(abase + row * 128 + ((q ^ (row & 7)) << 4),
                 A + (size_t)(m0 + row) * K + kc * 64 + q * 8);
        }
#pragma unroll
        for (int p = 0; p < 2; p++) {
            int idx = p * 256 + tid;
            int l = idx >> 8, rem = idx & 255, row = rem >> 3, q = rem & 7;
            cp16(bbase + l * (BN * 128) + row * 128 + ((q ^ (row & 7)) << 4),
                 BL + (size_t)l * LSTR + (size_t)(n0 + row) * K + kc * 64 + q * 8);
        }
        CP_COMMIT();
    };

    float acc[2][2][NT4][4] = {};   // [digit][m-tile][n-tile][frag]

    load_chunk(0, 0);
    load_chunk(1, 1);

    for (int c = 0; c < NCH; c++) {
        int stg = c % 3;
        if (c + 2 < NCH) { load_chunk(c + 2, (c + 2) % 3); CP_WAIT(2); }
        else if (c + 1 < NCH) { CP_WAIT(1); }
        else { CP_WAIT(0); }
        __syncthreads();

        uint32_t abase = sb + stg * STAGE;
        uint32_t bbase = abase + ABYTES;
        int j = lane >> 3, r = lane & 7;

#pragma unroll
        for (int ks = 0; ks < 4; ks++) {   // k16 steps within 64-chunk
            uint32_t a[2][4];
#pragma unroll
            for (int mt = 0; mt < 2; mt++) {
                int row = wm + mt * 16 + ((j & 1) << 3) + r;
                int slot = (ks * 2 + (j >> 1)) ^ (row & 7);
                ldsm4(a[mt], abase + row * 128 + slot * 16);
            }
#pragma unroll
            for (int l = 0; l < 2; l++) {
                if (WHICH == 1) {
                    uint32_t b[4];
                    int row = wn + ((j >> 1) << 3) + r;
                    int slot = (ks * 2 + (j & 1)) ^ (row & 7);
                    ldsm4(b, bbase + l * (BN * 128) + row * 128 + slot * 16);
#pragma unroll
                    for (int mt = 0; mt < 2; mt++) {
                        hmma16816(acc[l][mt][0], a[mt], &b[0]);
                        hmma16816(acc[l][mt][1], a[mt], &b[2]);
                    }
                } else {
                    uint32_t b[2];
                    int row = wn + r;
                    int slot = (ks * 2 + (j & 1)) ^ (row & 7);
                    ldsm2(b, bbase + l * (BN * 128) + row * 128 + slot * 16);
#pragma unroll
                    for (int mt = 0; mt < 2; mt++)
                        hmma16816(acc[l][mt][0], a[mt], b);
                }
            }
        }
        __syncthreads();
    }

    // ---- exact combine + fused LIF epilogue ----
    const double SCALE = 1.4901161193847656e-08;  // 2^-26
    int qr = lane >> 2, qc = (lane & 3) * 2;
#pragma unroll
    for (int mt = 0; mt < 2; mt++) {
#pragma unroll
        for (int h = 0; h < 2; h++) {
            int m = m0 + wm + mt * 16 + qr + h * 8;
#pragma unroll
            for (int nt = 0; nt < NT4; nt++) {
                int n = n0 + wn + nt * 8 + qc;
                double T0 = (double)acc[1][mt][nt][h * 2] * 4096.0 +
                            (double)acc[0][mt][nt][h * 2];
                double T1 = (double)acc[1][mt][nt][h * 2 + 1] * 4096.0 +
                            (double)acc[0][mt][nt][h * 2 + 1];
                float v0 = (float)(T0 * SCALE);
                float v1 = (float)(T1 * SCALE);
                size_t idx = (size_t)m * NOUT + n;
                if (WHICH == 1) {
                    float2 bv = *(const float2*)(b1 + n);
                    float2 fv = *(const float2*)(g_df2 + n);
                    float2 pv = *(float2*)(g_p2 + idx);
                    float p0 = pv.x * 0.9f + (v0 + bv.x) * fv.x;
                    float p1 = pv.y * 0.9f + (v1 + bv.y) * fv.y;
                    bool s0 = p0 > 0.8f, s1 = p1 > 0.8f;
                    *(float2*)(g_p2 + idx) = make_float2(s0 ? 0.f : p0, s1 ? 0.f : p1);
                    *(uint32_t*)(g_s2 + idx) =
                        (s0 ? 0x3C00u : 0u) | ((s1 ? 0x3C00u : 0u) << 16);
                } else {
                    float tw = g_tw[t];
                    float2 av = *(float2*)(g_acc + idx);
                    av.x += tw * v0;
                    av.y += tw * v1;
                    *(float2*)(g_acc + idx) = av;
                    if (t + 1 < NT) {
                        float2 xv = *(const float2*)(x + (size_t)m * (NT * NI) +
                                                     (size_t)(t + 1) * NI + n);
                        float2 fv = *(const float2*)(g_df1 + n);
                        float2 pv = *(float2*)(g_p1 + idx);
                        float p0 = pv.x * 0.9f + xv.x * fv.x;
                        float p1 = pv.y * 0.9f + xv.y * fv.y;
                        bool s0 = p0 > 1.0f, s1 = p1 > 1.0f;
                        *(float2*)(g_p1 + idx) = make_float2(s0 ? 0.f : p0, s1 ? 0.f : p1);
                        *(uint32_t*)(g_s1 + idx) =
                            (s0 ? 0x3C00u : 0u) | ((s1 ? 0x3C00u : 0u) << 16);
                    }
                }
            }
        }
    }
}

// Final: out = (acc + b2) * out_scale + out_bias  (sum_t tw == 1 absorbs b2).
__global__ void final_kernel(const float* __restrict__ b2, const float* __restrict__ osc,
                             const float* __restrict__ obi, float* __restrict__ out) {
    int idx = blockIdx.x * blockDim.x + threadIdx.x;
    int o = idx & (NO - 1);
    out[idx] = (g_acc[idx] + b2[o]) * osc[o] + obi[o];
}

// ---------------------------------------------------------------------------
extern "C" void kernel_launch(void* const* d_in, const int* in_sizes, int n_in,
                              void* d_out, int out_size) {
    const float* x   = (const float*)d_in[0];
    const float* cd1 = (const float*)d_in[1];
    const float* v1  = (const float*)d_in[2];
    const float* cd2 = (const float*)d_in[3];
    const float* v2  = (const float*)d_in[4];
    const float* W1  = (const float*)d_in[5];
    const float* b1  = (const float*)d_in[6];
    const float* W2  = (const float*)d_in[7];
    const float* b2  = (const float*)d_in[8];
    const float* osc = (const float*)d_in[9];
    const float* obi = (const float*)d_in[10];
    float* out = (float*)d_out;

    constexpr int SMEM1 = 3 * (128 * 128 + 2 * 32 * 128);  // 73728
    constexpr int SMEM2 = 3 * (64 * 128 + 2 * 32 * 128);   // 49152
    cudaFuncSetAttribute(snn_hmma<1>, cudaFuncAttributeMaxDynamicSharedMemorySize, SMEM1);
    cudaFuncSetAttribute(snn_hmma<2>, cudaFuncAttributeMaxDynamicSharedMemorySize, SMEM2);

    init_kernel<<<(NB * NH + 255) / 256, 256>>>(cd1, v1, cd2, v2);
    limbs_kernel<<<(NH * NI + 255) / 256, 256>>>(W1, W2);
    tw_kernel<<<1, 128>>>(v1);
    lif1_first<<<(NB * NI) / 256, 256>>>(x);

    for (int t = 0; t < NT; t++) {
        snn_hmma<1><<<dim3(NH / 32, NB / 128), 256, SMEM1>>>(b1, x, t);
        snn_hmma<2><<<dim3(NO / 32, NB / 64), 256, SMEM2>>>(b1, x, t);
    }

    final_kernel<<<(NB * NO) / 256, 256>>>(b2, osc, obi, out);
}